// round 3
// baseline (speedup 1.0000x reference)
#include <cuda_runtime.h>
#include <math_constants.h>

#define BB 8
#define CC 512
#define NN 1024
#define HH 8
#define DD 64

// Scratch (allocation-free: __device__ globals)
__device__ float  g_q[BB*HH*NN*DD];     // 16 MB: Q[b][h][n][d]
__device__ float  g_k[BB*HH*NN*DD];     // 16 MB: K[b][h][n][d]
__device__ float  g_attn[BB*NN*NN];     // 32 MB: sum over heads of softmax rows
__device__ double g_ksc[BB*NN];         // key_scores accumulators (fp64)
__device__ float  g_mp[BB*CC];          // max-pooled (B, C)

// ---------------------------------------------------------------------------
// Kernel 1: fused Q/K projection.  out[m=(b,n), j] = sum_c x[b,c,n]*W[j,c] + bias[j]
// ---------------------------------------------------------------------------
__global__ __launch_bounds__(256) void proj_kernel(const float* __restrict__ x,
                                                   const float* __restrict__ W,
                                                   const float* __restrict__ bias) {
    __shared__ float As[16][65];
    __shared__ float Bs[16][65];
    int tid = threadIdx.x;
    int tx = tid & 15, ty = tid >> 4;
    int j0 = blockIdx.x * 64;
    int m0 = blockIdx.y * 64;
    int b  = m0 >> 10;
    int n0 = m0 & 1023;
    const float* xb = x + (size_t)b * CC * NN;

    float acc[4][4];
    #pragma unroll
    for (int i = 0; i < 4; i++)
        #pragma unroll
        for (int j = 0; j < 4; j++) acc[i][j] = 0.f;

    for (int kb = 0; kb < CC; kb += 16) {
        #pragma unroll
        for (int p = 0; p < 4; p++) {
            int e = tid + p * 256;
            int kk = e >> 6, m = e & 63;
            As[kk][m] = xb[(kb + kk) * NN + n0 + m];
        }
        #pragma unroll
        for (int p = 0; p < 4; p++) {
            int e = tid + p * 256;
            int kk = e & 15, jl = e >> 4;
            Bs[kk][jl] = W[(size_t)(j0 + jl) * CC + kb + kk];
        }
        __syncthreads();
        #pragma unroll
        for (int kk = 0; kk < 16; kk++) {
            float a[4], bv[4];
            #pragma unroll
            for (int i = 0; i < 4; i++) a[i] = As[kk][ty * 4 + i];
            #pragma unroll
            for (int j = 0; j < 4; j++) bv[j] = Bs[kk][tx + j * 16];
            #pragma unroll
            for (int i = 0; i < 4; i++)
                #pragma unroll
                for (int j = 0; j < 4; j++) acc[i][j] += a[i] * bv[j];
        }
        __syncthreads();
    }

    #pragma unroll
    for (int j = 0; j < 4; j++) {
        int jg = j0 + tx + j * 16;
        float bsv = bias[jg];
        int head = (jg & 511) >> 6;
        int dd   = jg & 63;
        float* dst = (jg < 512) ? g_q : g_k;
        #pragma unroll
        for (int i = 0; i < 4; i++) {
            int n = n0 + ty * 4 + i;
            dst[((size_t)(b * HH + head) * NN + n) * DD + dd] = acc[i][j] + bsv;
        }
    }
}

// ---------------------------------------------------------------------------
// Kernel 2: scores + per-head softmax + head accumulation.
// ---------------------------------------------------------------------------
#define SMEM2 ((2080 + 8320 + 32 * 1024) * 4)

__global__ __launch_bounds__(256) void attn_kernel() {
    extern __shared__ float sm[];
    float* Qs = sm;               // [32][65]
    float* Ks = sm + 2080;        // [128][65]
    float* S  = sm + 2080 + 8320; // [32][1024]

    int tid = threadIdx.x;
    int b  = blockIdx.x >> 5;
    int q0 = (blockIdx.x & 31) << 5;
    int tx = tid & 31, ty = tid >> 5;

    for (int h = 0; h < HH; h++) {
        const float* Qg = g_q + ((size_t)(b * HH + h) * NN + q0) * DD;
        const float* Kg = g_k + (size_t)(b * HH + h) * NN * DD;

        #pragma unroll
        for (int p = 0; p < 8; p++) {
            int e = tid + p * 256;
            int r = e >> 6, dd = e & 63;
            Qs[r * 65 + dd] = Qg[r * DD + dd];
        }

        for (int kt = 0; kt < 8; kt++) {
            int k0 = kt * 128;
            __syncthreads();
            #pragma unroll
            for (int p = 0; p < 32; p++) {
                int e = tid + p * 256;
                int r = e >> 6, dd = e & 63;
                Ks[r * 65 + dd] = Kg[(k0 + r) * DD + dd];
            }
            __syncthreads();

            float acc[4][4] = {};
            #pragma unroll
            for (int kk = 0; kk < 64; kk++) {
                float a[4], bv[4];
                #pragma unroll
                for (int i = 0; i < 4; i++) a[i] = Qs[(ty * 4 + i) * 65 + kk];
                #pragma unroll
                for (int j = 0; j < 4; j++) bv[j] = Ks[(tx + j * 32) * 65 + kk];
                #pragma unroll
                for (int i = 0; i < 4; i++)
                    #pragma unroll
                    for (int j = 0; j < 4; j++) acc[i][j] += a[i] * bv[j];
            }
            #pragma unroll
            for (int i = 0; i < 4; i++)
                #pragma unroll
                for (int j = 0; j < 4; j++)
                    S[(ty * 4 + i) * 1024 + k0 + tx + j * 32] = acc[i][j] * 0.125f;
        }
        __syncthreads();

        #pragma unroll
        for (int r = 0; r < 4; r++) {
            int row = ty * 4 + r;
            float* Sr = S + row * 1024;
            float m = -CUDART_INF_F;
            for (int c = tx; c < 1024; c += 32) m = fmaxf(m, Sr[c]);
            #pragma unroll
            for (int o = 16; o; o >>= 1) m = fmaxf(m, __shfl_xor_sync(~0u, m, o));
            float s = 0.f;
            for (int c = tx; c < 1024; c += 32) { float e = expf(Sr[c] - m); Sr[c] = e; s += e; }
            #pragma unroll
            for (int o = 16; o; o >>= 1) s += __shfl_xor_sync(~0u, s, o);
            float inv = 1.f / s;
            float* gp = g_attn + ((size_t)(b * NN + q0 + row)) * NN;
            if (h == 0) { for (int c = tx; c < 1024; c += 32) gp[c]  = Sr[c] * inv; }
            else        { for (int c = tx; c < 1024; c += 32) gp[c] += Sr[c] * inv; }
        }
        __syncthreads();
    }
}

// ---------------------------------------------------------------------------
// Kernel 3: w2 softmax + column mean, in FP64 for rank stability.
// ---------------------------------------------------------------------------
__global__ void zero_ks_kernel() {
    g_ksc[blockIdx.x * 1024 + threadIdx.x] = 0.0;
}

__global__ __launch_bounds__(256) void wsoft_kernel() {
    __shared__ double red[8];
    int tid = threadIdx.x;
    int b  = blockIdx.x >> 6;
    int q0 = (blockIdx.x & 63) << 4;
    int lane = tid & 31, warp = tid >> 5;
    double acc[4] = {0.0, 0.0, 0.0, 0.0};

    for (int r = 0; r < 16; r++) {
        const float* row = g_attn + ((size_t)(b * NN + q0 + r)) * NN;
        double v[4];
        #pragma unroll
        for (int j = 0; j < 4; j++) v[j] = (double)row[tid + j * 256] * (1.0 / 256.0);

        double m = fmax(fmax(v[0], v[1]), fmax(v[2], v[3]));
        #pragma unroll
        for (int o = 16; o; o >>= 1) m = fmax(m, __shfl_xor_sync(~0u, m, o));
        if (lane == 0) red[warp] = m;
        __syncthreads();
        double mm = red[0];
        #pragma unroll
        for (int w = 1; w < 8; w++) mm = fmax(mm, red[w]);
        __syncthreads();

        double e[4]; double s = 0.0;
        #pragma unroll
        for (int j = 0; j < 4; j++) { e[j] = exp(v[j] - mm); s += e[j]; }
        #pragma unroll
        for (int o = 16; o; o >>= 1) s += __shfl_xor_sync(~0u, s, o);
        if (lane == 0) red[warp] = s;
        __syncthreads();
        double ss = 0.0;
        #pragma unroll
        for (int w = 0; w < 8; w++) ss += red[w];
        __syncthreads();

        double inv = 1.0 / ss;
        #pragma unroll
        for (int j = 0; j < 4; j++) acc[j] += e[j] * inv;
    }
    #pragma unroll
    for (int j = 0; j < 4; j++)
        atomicAdd(&g_ksc[b * NN + tid + j * 256], acc[j] * (1.0 / 1024.0));
}

// ---------------------------------------------------------------------------
// Kernel 4: top-8 per batch. CRITICAL: compare in FP32 (matching the
// reference's fp32 materialization of key_scores, whose ulp ~1.16e-10 exceeds
// the rank-8/9 gaps -> exact ties), tie-break lowest index, then max-pool.
// ---------------------------------------------------------------------------
__global__ __launch_bounds__(256) void topk_kernel(const float* __restrict__ x) {
    __shared__ float bvv[8];
    __shared__ int   bii[8];
    __shared__ int   sel[8];
    __shared__ int   sbi;
    int b = blockIdx.x;
    int tid = threadIdx.x;
    int lane = tid & 31, warp = tid >> 5;

    float v[4]; int idx[4];
    #pragma unroll
    for (int j = 0; j < 4; j++) {
        idx[j] = tid + j * 256;
        v[j] = (float)g_ksc[b * NN + idx[j]];   // round-to-nearest fp32, like ref
    }

    for (int it = 0; it < 8; it++) {
        float mv = v[0]; int mi = idx[0];
        #pragma unroll
        for (int j = 1; j < 4; j++)
            if (v[j] > mv || (v[j] == mv && idx[j] < mi)) { mv = v[j]; mi = idx[j]; }
        #pragma unroll
        for (int o = 16; o; o >>= 1) {
            float ov = __shfl_xor_sync(~0u, mv, o);
            int   oi = __shfl_xor_sync(~0u, mi, o);
            if (ov > mv || (ov == mv && oi < mi)) { mv = ov; mi = oi; }
        }
        if (lane == 0) { bvv[warp] = mv; bii[warp] = mi; }
        __syncthreads();
        if (tid == 0) {
            float m2 = bvv[0]; int i2 = bii[0];
            for (int w = 1; w < 8; w++)
                if (bvv[w] > m2 || (bvv[w] == m2 && bii[w] < i2)) { m2 = bvv[w]; i2 = bii[w]; }
            sel[it] = i2; sbi = i2;
        }
        __syncthreads();
        int si = sbi;
        #pragma unroll
        for (int j = 0; j < 4; j++) if (idx[j] == si) v[j] = -CUDART_INF_F;
        __syncthreads();
    }

    for (int c = tid; c < CC; c += 256) {
        const float* xb = x + ((size_t)(b * CC + c)) * NN;
        float m = -CUDART_INF_F;
        #pragma unroll
        for (int j = 0; j < 8; j++) m = fmaxf(m, xb[sel[j]]);
        g_mp[b * CC + c] = m;
    }
}

// ---------------------------------------------------------------------------
// Kernel 5: out = x + max_pooled broadcast
// ---------------------------------------------------------------------------
__global__ void add_kernel(const float* __restrict__ x, float* __restrict__ out) {
    int i = blockIdx.x * 256 + threadIdx.x;
    int bc = i >> 10;
    out[i] = x[i] + g_mp[bc];
}

// ---------------------------------------------------------------------------
extern "C" void kernel_launch(void* const* d_in, const int* in_sizes, int n_in,
                              void* d_out, int out_size) {
    const float* x    = (const float*)d_in[0];
    const float* W    = (const float*)d_in[1];
    const float* bias = (const float*)d_in[2];
    float* out = (float*)d_out;

    cudaFuncSetAttribute(attn_kernel, cudaFuncAttributeMaxDynamicSharedMemorySize, SMEM2);

    proj_kernel<<<dim3(16, 128), 256>>>(x, W, bias);
    attn_kernel<<<256, 256, SMEM2>>>();
    zero_ks_kernel<<<8, 1024>>>();
    wsoft_kernel<<<512, 256>>>();
    topk_kernel<<<8, 256>>>(x);
    add_kernel<<<(BB * CC * NN) / 256, 256>>>(x, out);
}

// round 4
// speedup vs baseline: 1.2607x; 1.2607x over previous
#include <cuda_runtime.h>
#include <math_constants.h>

#define BB 8
#define CC 512
#define NN 1024
#define HH 8
#define DD 64

// Scratch (allocation-free: __device__ globals)
__device__ float  g_q[BB*HH*NN*DD];     // 16 MB: Q[b][h][n][d]
__device__ float  g_k[BB*HH*NN*DD];     // 16 MB: K[b][h][n][d]
__device__ float  g_attn[BB*NN*NN];     // 32 MB: sum over heads of softmax rows
__device__ double g_ksc[BB*NN];         // key_scores accumulators (fp64)
__device__ float  g_mp[BB*CC];          // max-pooled (B, C)

// ---------------------------------------------------------------------------
// Kernel 1: fused Q/K projection.  out[m=(b,n), j] = sum_c x[b,c,n]*W[j,c] + bias[j]
// ---------------------------------------------------------------------------
__global__ __launch_bounds__(256) void proj_kernel(const float* __restrict__ x,
                                                   const float* __restrict__ W,
                                                   const float* __restrict__ bias) {
    __shared__ float As[16][65];
    __shared__ float Bs[16][65];
    int tid = threadIdx.x;
    int tx = tid & 15, ty = tid >> 4;
    int j0 = blockIdx.x * 64;
    int m0 = blockIdx.y * 64;
    int b  = m0 >> 10;
    int n0 = m0 & 1023;
    const float* xb = x + (size_t)b * CC * NN;

    float acc[4][4];
    #pragma unroll
    for (int i = 0; i < 4; i++)
        #pragma unroll
        for (int j = 0; j < 4; j++) acc[i][j] = 0.f;

    for (int kb = 0; kb < CC; kb += 16) {
        #pragma unroll
        for (int p = 0; p < 4; p++) {
            int e = tid + p * 256;
            int kk = e >> 6, m = e & 63;
            As[kk][m] = xb[(kb + kk) * NN + n0 + m];
        }
        #pragma unroll
        for (int p = 0; p < 4; p++) {
            int e = tid + p * 256;
            int kk = e & 15, jl = e >> 4;
            Bs[kk][jl] = W[(size_t)(j0 + jl) * CC + kb + kk];
        }
        __syncthreads();
        #pragma unroll
        for (int kk = 0; kk < 16; kk++) {
            float a[4], bv[4];
            #pragma unroll
            for (int i = 0; i < 4; i++) a[i] = As[kk][ty * 4 + i];
            #pragma unroll
            for (int j = 0; j < 4; j++) bv[j] = Bs[kk][tx + j * 16];
            #pragma unroll
            for (int i = 0; i < 4; i++)
                #pragma unroll
                for (int j = 0; j < 4; j++) acc[i][j] += a[i] * bv[j];
        }
        __syncthreads();
    }

    #pragma unroll
    for (int j = 0; j < 4; j++) {
        int jg = j0 + tx + j * 16;
        float bsv = bias[jg];
        int head = (jg & 511) >> 6;
        int dd   = jg & 63;
        float* dst = (jg < 512) ? g_q : g_k;
        #pragma unroll
        for (int i = 0; i < 4; i++) {
            int n = n0 + ty * 4 + i;
            dst[((size_t)(b * HH + head) * NN + n) * DD + dd] = acc[i][j] + bsv;
        }
    }
}

// ---------------------------------------------------------------------------
// Kernel 2: scores + per-head softmax + head accumulation.
// ---------------------------------------------------------------------------
#define SMEM2 ((2080 + 8320 + 32 * 1024) * 4)

__global__ __launch_bounds__(256) void attn_kernel() {
    extern __shared__ float sm[];
    float* Qs = sm;               // [32][65]
    float* Ks = sm + 2080;        // [128][65]
    float* S  = sm + 2080 + 8320; // [32][1024]

    int tid = threadIdx.x;
    int b  = blockIdx.x >> 5;
    int q0 = (blockIdx.x & 31) << 5;
    int tx = tid & 31, ty = tid >> 5;

    for (int h = 0; h < HH; h++) {
        const float* Qg = g_q + ((size_t)(b * HH + h) * NN + q0) * DD;
        const float* Kg = g_k + (size_t)(b * HH + h) * NN * DD;

        #pragma unroll
        for (int p = 0; p < 8; p++) {
            int e = tid + p * 256;
            int r = e >> 6, dd = e & 63;
            Qs[r * 65 + dd] = Qg[r * DD + dd];
        }

        for (int kt = 0; kt < 8; kt++) {
            int k0 = kt * 128;
            __syncthreads();
            #pragma unroll
            for (int p = 0; p < 32; p++) {
                int e = tid + p * 256;
                int r = e >> 6, dd = e & 63;
                Ks[r * 65 + dd] = Kg[(k0 + r) * DD + dd];
            }
            __syncthreads();

            float acc[4][4] = {};
            #pragma unroll
            for (int kk = 0; kk < 64; kk++) {
                float a[4], bv[4];
                #pragma unroll
                for (int i = 0; i < 4; i++) a[i] = Qs[(ty * 4 + i) * 65 + kk];
                #pragma unroll
                for (int j = 0; j < 4; j++) bv[j] = Ks[(tx + j * 32) * 65 + kk];
                #pragma unroll
                for (int i = 0; i < 4; i++)
                    #pragma unroll
                    for (int j = 0; j < 4; j++) acc[i][j] += a[i] * bv[j];
            }
            #pragma unroll
            for (int i = 0; i < 4; i++)
                #pragma unroll
                for (int j = 0; j < 4; j++)
                    S[(ty * 4 + i) * 1024 + k0 + tx + j * 32] = acc[i][j] * 0.125f;
        }
        __syncthreads();

        #pragma unroll
        for (int r = 0; r < 4; r++) {
            int row = ty * 4 + r;
            float* Sr = S + row * 1024;
            float m = -CUDART_INF_F;
            for (int c = tx; c < 1024; c += 32) m = fmaxf(m, Sr[c]);
            #pragma unroll
            for (int o = 16; o; o >>= 1) m = fmaxf(m, __shfl_xor_sync(~0u, m, o));
            float s = 0.f;
            for (int c = tx; c < 1024; c += 32) { float e = expf(Sr[c] - m); Sr[c] = e; s += e; }
            #pragma unroll
            for (int o = 16; o; o >>= 1) s += __shfl_xor_sync(~0u, s, o);
            float inv = 1.f / s;
            float* gp = g_attn + ((size_t)(b * NN + q0 + row)) * NN;
            if (h == 0) { for (int c = tx; c < 1024; c += 32) gp[c]  = Sr[c] * inv; }
            else        { for (int c = tx; c < 1024; c += 32) gp[c] += Sr[c] * inv; }
        }
        __syncthreads();
    }
}

// ---------------------------------------------------------------------------
// Kernel 3: w2 softmax + column mean in FP64.
// Logits x = attn/256 are provably in [0, 1/32] (attn = sum of 8 probs <= 8),
// so: no max-subtraction needed (softmax is shift-invariant, no overflow), and
// exp(x) = degree-6 Taylor poly, |err| <= (1/32)^7/5040 ~ 6e-15 -- far below
// the fp32 half-ulp (~6e-8 rel) that decides the top-k ranking.
// ---------------------------------------------------------------------------
__global__ void zero_ks_kernel() {
    g_ksc[blockIdx.x * 1024 + threadIdx.x] = 0.0;
}

__device__ __forceinline__ double exp_small(double xv) {
    // exp(xv) for xv in [0, 0.03125], degree-6 Taylor (Horner)
    double p = 1.0 / 720.0;
    p = fma(p, xv, 1.0 / 120.0);
    p = fma(p, xv, 1.0 / 24.0);
    p = fma(p, xv, 1.0 / 6.0);
    p = fma(p, xv, 0.5);
    p = fma(p, xv, 1.0);
    p = fma(p, xv, 1.0);
    return p;
}

__global__ __launch_bounds__(256) void wsoft_kernel() {
    __shared__ double red[8];
    int tid = threadIdx.x;
    int b  = blockIdx.x >> 6;
    int q0 = (blockIdx.x & 63) << 4;
    int lane = tid & 31, warp = tid >> 5;
    double acc[4] = {0.0, 0.0, 0.0, 0.0};

    for (int r = 0; r < 16; r++) {
        const float* row = g_attn + ((size_t)(b * NN + q0 + r)) * NN;
        double e[4]; double s = 0.0;
        #pragma unroll
        for (int j = 0; j < 4; j++) {
            double xv = (double)row[tid + j * 256] * (1.0 / 256.0);
            e[j] = exp_small(xv);
            s += e[j];
        }
        #pragma unroll
        for (int o = 16; o; o >>= 1) s += __shfl_xor_sync(~0u, s, o);
        if (lane == 0) red[warp] = s;
        __syncthreads();
        double ss = red[0] + red[1] + red[2] + red[3]
                  + red[4] + red[5] + red[6] + red[7];
        __syncthreads();

        double inv = 1.0 / ss;
        #pragma unroll
        for (int j = 0; j < 4; j++) acc[j] += e[j] * inv;
    }
    #pragma unroll
    for (int j = 0; j < 4; j++)
        atomicAdd(&g_ksc[b * NN + tid + j * 256], acc[j] * (1.0 / 1024.0));
}

// ---------------------------------------------------------------------------
// Kernel 4: top-8 per batch, FP32 compares (matches reference's fp32
// quantization of key_scores; ties broken by lower index), then max-pool.
// ---------------------------------------------------------------------------
__global__ __launch_bounds__(256) void topk_kernel(const float* __restrict__ x) {
    __shared__ float bvv[8];
    __shared__ int   bii[8];
    __shared__ int   sel[8];
    __shared__ int   sbi;
    int b = blockIdx.x;
    int tid = threadIdx.x;
    int lane = tid & 31, warp = tid >> 5;

    float v[4]; int idx[4];
    #pragma unroll
    for (int j = 0; j < 4; j++) {
        idx[j] = tid + j * 256;
        v[j] = (float)g_ksc[b * NN + idx[j]];   // round-to-nearest fp32, like ref
    }

    for (int it = 0; it < 8; it++) {
        float mv = v[0]; int mi = idx[0];
        #pragma unroll
        for (int j = 1; j < 4; j++)
            if (v[j] > mv || (v[j] == mv && idx[j] < mi)) { mv = v[j]; mi = idx[j]; }
        #pragma unroll
        for (int o = 16; o; o >>= 1) {
            float ov = __shfl_xor_sync(~0u, mv, o);
            int   oi = __shfl_xor_sync(~0u, mi, o);
            if (ov > mv || (ov == mv && oi < mi)) { mv = ov; mi = oi; }
        }
        if (lane == 0) { bvv[warp] = mv; bii[warp] = mi; }
        __syncthreads();
        if (tid == 0) {
            float m2 = bvv[0]; int i2 = bii[0];
            for (int w = 1; w < 8; w++)
                if (bvv[w] > m2 || (bvv[w] == m2 && bii[w] < i2)) { m2 = bvv[w]; i2 = bii[w]; }
            sel[it] = i2; sbi = i2;
        }
        __syncthreads();
        int si = sbi;
        #pragma unroll
        for (int j = 0; j < 4; j++) if (idx[j] == si) v[j] = -CUDART_INF_F;
        __syncthreads();
    }

    for (int c = tid; c < CC; c += 256) {
        const float* xb = x + ((size_t)(b * CC + c)) * NN;
        float m = -CUDART_INF_F;
        #pragma unroll
        for (int j = 0; j < 8; j++) m = fmaxf(m, xb[sel[j]]);
        g_mp[b * CC + c] = m;
    }
}

// ---------------------------------------------------------------------------
// Kernel 5: out = x + max_pooled broadcast
// ---------------------------------------------------------------------------
__global__ void add_kernel(const float* __restrict__ x, float* __restrict__ out) {
    int i = blockIdx.x * 256 + threadIdx.x;
    int bc = i >> 10;
    out[i] = x[i] + g_mp[bc];
}

// ---------------------------------------------------------------------------
extern "C" void kernel_launch(void* const* d_in, const int* in_sizes, int n_in,
                              void* d_out, int out_size) {
    const float* x    = (const float*)d_in[0];
    const float* W    = (const float*)d_in[1];
    const float* bias = (const float*)d_in[2];
    float* out = (float*)d_out;

    cudaFuncSetAttribute(attn_kernel, cudaFuncAttributeMaxDynamicSharedMemorySize, SMEM2);

    proj_kernel<<<dim3(16, 128), 256>>>(x, W, bias);
    attn_kernel<<<256, 256, SMEM2>>>();
    zero_ks_kernel<<<8, 1024>>>();
    wsoft_kernel<<<512, 256>>>();
    topk_kernel<<<8, 256>>>(x);
    add_kernel<<<(BB * CC * NN) / 256, 256>>>(x, out);
}